// round 1
// baseline (speedup 1.0000x reference)
#include <cuda_runtime.h>
#include <stdint.h>

#define D        64
#define KCB      1024
#define MT       128     // rows per block
#define KC       64      // candidates per chunk
#define NTH      256
#define XS_STRIDE 65     // padded x tile stride (conflict-free reads/writes)
#define CS_STRIDE 68     // padded transposed codebook stride (8B-aligned pair loads)

__device__ float g_cnorm[KCB];
__device__ float g_part[8192];

__device__ __forceinline__ unsigned long long pack2(float a, float b) {
    unsigned long long r;
    asm("mov.b64 %0, {%1, %2};" : "=l"(r)
        : "r"(__float_as_uint(a)), "r"(__float_as_uint(b)));
    return r;
}
__device__ __forceinline__ void unpack2(unsigned long long v, float& a, float& b) {
    unsigned int x, y;
    asm("mov.b64 {%0, %1}, %2;" : "=r"(x), "=r"(y) : "l"(v));
    a = __uint_as_float(x); b = __uint_as_float(y);
}
__device__ __forceinline__ void fma2(unsigned long long& acc,
                                     unsigned long long a, unsigned long long b) {
    asm("fma.rn.f32x2 %0, %1, %2, %0;" : "+l"(acc) : "l"(a), "l"(b));
}

// Prologue: cnorm[k] = sum_d c[k][d]^2 (mul then add, matching ref's sum(c*c))
__global__ void vq_prep(const float* __restrict__ cb) {
    int k = blockIdx.x * blockDim.x + threadIdx.x;
    if (k < KCB) {
        float s = 0.f;
        #pragma unroll
        for (int d = 0; d < D; d++) {
            float v = cb[k * D + d];
            s = __fadd_rn(s, __fmul_rn(v, v));
        }
        g_cnorm[k] = s;
    }
}

__global__ void __launch_bounds__(NTH, 2)
vq_main(const float* __restrict__ inp, const float* __restrict__ cb,
        float* __restrict__ out, int N,
        long long loss_off, long long idx_off) {
    extern __shared__ float sm[];
    float* xs   = sm;                        // MT * XS_STRIDE
    float* cs   = xs + MT * XS_STRIDE;       // D * CS_STRIDE (cs[d][cand])
    float* sxn  = cs + D * CS_STRIDE;        // MT row norms
    int*   sidx = (int*)(sxn + MT);          // MT best indices
    float* sred = (float*)(sidx + MT);       // 32 reduction slots

    const int tid = threadIdx.x;
    const int tx = tid & 7;                  // candidate group: 8 cands
    const int ty = tid >> 3;                 // row group: 4 rows
    const int r0 = ty * 4;
    const int c0 = tx * 8;
    const long long rowbase = (long long)blockIdx.x * MT;

    // ---- load X tile (coalesced, conflict-free smem writes) ----
    const float* ginp = inp + rowbase * D;
    #pragma unroll
    for (int i = 0; i < MT * D / NTH; i++) {
        int e = tid + i * NTH;
        xs[(e >> 6) * XS_STRIDE + (e & 63)] = ginp[e];
    }
    __syncthreads();

    // per-row xnorm (mul then add, matching ref's sum(x*x))
    if (tid < MT) {
        float s = 0.f;
        #pragma unroll
        for (int d = 0; d < D; d++) {
            float v = xs[tid * XS_STRIDE + d];
            s = __fadd_rn(s, __fmul_rn(v, v));
        }
        sxn[tid] = s;
    }
    __syncthreads();

    float xn[4];
    #pragma unroll
    for (int j = 0; j < 4; j++) xn[j] = sxn[r0 + j];

    float bestv[4]; int besti[4];
    #pragma unroll
    for (int j = 0; j < 4; j++) { bestv[j] = 3.4e38f; besti[j] = 0; }

    const float* xrow = xs + r0 * XS_STRIDE;

    for (int ch = 0; ch < KCB / KC; ch++) {
        // ---- load codebook chunk transposed: cs[d][cand] ----
        const float* gcb = cb + (long long)ch * KC * D;
        __syncthreads();
        #pragma unroll
        for (int i = 0; i < KC * D / NTH; i++) {
            int e = tid + i * NTH;
            cs[(e & 63) * CS_STRIDE + (e >> 6)] = gcb[e];
        }
        __syncthreads();

        unsigned long long acc[4][4];
        #pragma unroll
        for (int j = 0; j < 4; j++)
            #pragma unroll
            for (int q = 0; q < 4; q++) acc[j][q] = 0ULL;

        // ---- main FMA loop: 4 rows x 8 cands (4 packed pairs) per thread ----
        #pragma unroll 8
        for (int d = 0; d < D; d++) {
            unsigned long long cp[4];
            const unsigned long long* cp64 =
                (const unsigned long long*)(cs + d * CS_STRIDE + c0);
            #pragma unroll
            for (int q = 0; q < 4; q++) cp[q] = cp64[q];
            #pragma unroll
            for (int j = 0; j < 4; j++) {
                float xv = xrow[j * XS_STRIDE + d];
                unsigned long long xp = pack2(xv, xv);
                #pragma unroll
                for (int q = 0; q < 4; q++) fma2(acc[j][q], xp, cp[q]);
            }
        }

        // ---- epilogue: d2 = (xnorm - 2*dot) + cnorm, first-min argmin ----
        const int kb = ch * KC + c0;
        #pragma unroll
        for (int q = 0; q < 4; q++) {
            float cn0 = g_cnorm[kb + 2 * q];
            float cn1 = g_cnorm[kb + 2 * q + 1];
            #pragma unroll
            for (int j = 0; j < 4; j++) {
                float d0, d1; unpack2(acc[j][q], d0, d1);
                float t0 = __fadd_rn(__fmaf_rn(-2.0f, d0, xn[j]), cn0);
                float t1 = __fadd_rn(__fmaf_rn(-2.0f, d1, xn[j]), cn1);
                if (t0 < bestv[j]) { bestv[j] = t0; besti[j] = kb + 2 * q; }
                if (t1 < bestv[j]) { bestv[j] = t1; besti[j] = kb + 2 * q + 1; }
            }
        }
    }

    // ---- reduce argmin across the 8 candidate-group lanes (prefer lower idx on ties) ----
    #pragma unroll
    for (int off = 1; off < 8; off <<= 1) {
        #pragma unroll
        for (int j = 0; j < 4; j++) {
            float ov = __shfl_xor_sync(0xffffffffu, bestv[j], off);
            int   oi = __shfl_xor_sync(0xffffffffu, besti[j], off);
            if (ov < bestv[j] || (ov == bestv[j] && oi < besti[j])) {
                bestv[j] = ov; besti[j] = oi;
            }
        }
    }
    if (tx == 0) {
        #pragma unroll
        for (int j = 0; j < 4; j++) sidx[r0 + j] = besti[j];
    }
    __syncthreads();

    // ---- writeback: quantized_ste = x + (q - x); accumulate (q-x)^2 ----
    float lsum = 0.f;
    #pragma unroll
    for (int i = 0; i < MT * D / NTH; i++) {
        int e = tid + i * NTH;
        int r = e >> 6, d = e & 63;
        int idx = sidx[r];
        float qv = cb[(long long)idx * D + d];
        float xv = xs[r * XS_STRIDE + d];
        float diff = __fsub_rn(qv, xv);
        out[rowbase * D + e] = __fadd_rn(xv, diff);
        lsum = __fmaf_rn(diff, diff, lsum);
    }

    if (idx_off >= 0 && tid < MT) {
        out[idx_off + rowbase + tid] = (float)sidx[tid];
    }

    // block reduction of loss partial (deterministic)
    #pragma unroll
    for (int off = 16; off; off >>= 1)
        lsum += __shfl_xor_sync(0xffffffffu, lsum, off);
    if ((tid & 31) == 0) sred[tid >> 5] = lsum;
    __syncthreads();
    if (tid == 0) {
        float s = 0.f;
        #pragma unroll
        for (int w = 0; w < NTH / 32; w++) s += sred[w];
        g_part[blockIdx.x] = s;
    }
}

__global__ void vq_final(float* __restrict__ out, int nb,
                         long long loss_off, double inv_cnt) {
    __shared__ double sd[256];
    double s = 0.0;
    for (int i = threadIdx.x; i < nb; i += blockDim.x) s += (double)g_part[i];
    sd[threadIdx.x] = s;
    __syncthreads();
    for (int k = 128; k; k >>= 1) {
        if (threadIdx.x < k) sd[threadIdx.x] += sd[threadIdx.x + k];
        __syncthreads();
    }
    if (threadIdx.x == 0) {
        float m = (float)(sd[0] * inv_cnt);
        // loss = q_latent + 0.25 * e_latent, both equal m
        out[loss_off] = __fadd_rn(m, __fmul_rn(0.25f, m));
    }
}

extern "C" void kernel_launch(void* const* d_in, const int* in_sizes, int n_in,
                              void* d_out, int out_size) {
    const float* inp = (const float*)d_in[0];
    const float* cb  = (const float*)d_in[1];
    float* out = (float*)d_out;

    const int N = in_sizes[0] / D;           // 131072
    const long long sq = (long long)N * D;   // quantized element count
    long long loss_off = -1, idx_off = -1;
    if ((long long)out_size >= sq + 1)       loss_off = sq;
    if ((long long)out_size >= sq + 1 + N)   idx_off = sq + 1;

    const int nb = (N + MT - 1) / MT;
    const int smem = (MT * XS_STRIDE + D * CS_STRIDE + MT) * 4 + MT * 4 + 32 * 4;

    cudaFuncSetAttribute(vq_main, cudaFuncAttributeMaxDynamicSharedMemorySize, smem);

    vq_prep<<<(KCB + 255) / 256, 256>>>(cb);
    vq_main<<<nb, NTH, smem>>>(inp, cb, out, N, loss_off, idx_off);
    if (loss_off >= 0) {
        vq_final<<<1, 256>>>(out, nb, loss_off, 1.0 / (double)((long long)N * D));
    }
}

// round 5
// speedup vs baseline: 1.3301x; 1.3301x over previous
#include <cuda_runtime.h>
#include <cuda_bf16.h>
#include <stdint.h>

#define D     64
#define KCB   1024
#define MT    256          // rows per block
#define NTH   256          // 8 warps
#define CHC   64           // candidates per chunk
#define NCH   (KCB/CHC)    // 16

// ---------------- device globals ----------------
__device__ __align__(16) __nv_bfloat16 g_c0[KCB * D];   // permuted bf16 split 0
__device__ __align__(16) __nv_bfloat16 g_c1[KCB * D];   // split 1
__device__ __align__(16) __nv_bfloat16 g_c2[KCB * D];   // split 2
__device__ float g_cnorm[KCB];
__device__ float g_part[1024];

// ---------------- smem layout (bytes) ----------------
#define OFF_XF    0                       // fp32 x, 256 rows * 65 floats
#define OFF_XB0   66560                   // bf16 x0, 256 rows * 128B
#define OFF_XB1   99328                   // bf16 x1
#define OFF_XB2   132096                  // bf16 x2
#define OFF_CS    164864                  // 2 bufs * (c0|c1|c2, 8KB each) = 49152
#define OFF_CN    214016                  // 1024 f32
#define OFF_XN    218112                  // 256 f32
#define OFF_SIDX  219136                  // 256 i32
#define OFF_SRED  220160                  // 8 f32
#define SMEM_DYN  220192

__device__ __forceinline__ uint32_t smem_u32(const void* p) {
    uint32_t a;
    asm("{ .reg .u64 t; cvta.to.shared.u64 t, %1; cvt.u32.u64 %0, t; }"
        : "=r"(a) : "l"(p));
    return a;
}

#define LDS64(r0_, r1_, a) \
    asm volatile("ld.shared.v2.b32 {%0,%1}, [%2];" : "=r"(r0_), "=r"(r1_) : "r"(a))

#define MMA_BF16(dd, aa, b0_, b1_) \
    asm volatile("mma.sync.aligned.m16n8k16.row.col.f32.bf16.bf16.f32 " \
        "{%0,%1,%2,%3}, {%4,%5,%6,%7}, {%8,%9}, {%0,%1,%2,%3};" \
        : "+f"((dd)[0]), "+f"((dd)[1]), "+f"((dd)[2]), "+f"((dd)[3]) \
        : "r"((aa)[0]), "r"((aa)[1]), "r"((aa)[2]), "r"((aa)[3]), \
          "r"(b0_), "r"(b1_))

#define CP_ASYNC16(dst, src) \
    asm volatile("cp.async.cg.shared.global [%0], [%1], 16;" \
                 :: "r"(dst), "l"(src) : "memory")
#define CP_COMMIT() asm volatile("cp.async.commit_group;" ::: "memory")

// ---------------- prep: 3-way bf16 split of codebook (permuted) + exact cnorm ----
__global__ void vq_prep(const float* __restrict__ cb) {
    int k = blockIdx.x * blockDim.x + threadIdx.x;
    if (k >= KCB) return;
    float s = 0.f;
    #pragma unroll
    for (int d = 0; d < D; d++) {
        float v = cb[k * D + d];
        s = __fadd_rn(s, __fmul_rn(v, v));
        __nv_bfloat16 h0 = __float2bfloat16_rn(v);
        float r1 = __fsub_rn(v, __bfloat162float(h0));
        __nv_bfloat16 h1 = __float2bfloat16_rn(r1);
        float r2 = __fsub_rn(r1, __bfloat162float(h1));
        __nv_bfloat16 h2 = __float2bfloat16_rn(r2);
        int ks = d >> 4, w16 = d & 15;
        int hi8 = w16 >> 3, tig = (w16 & 7) >> 1, sub = d & 1;
        int pos = (4 * ks + tig) * 4 + hi8 * 2 + sub;
        g_c0[k * D + pos] = h0;
        g_c1[k * D + pos] = h1;
        g_c2[k * D + pos] = h2;
    }
    g_cnorm[k] = s;
}

// issue async copy of chunk ch into buffer buf (256 threads, 6x16B each = 24KB)
__device__ __forceinline__ void issue_chunk(uint32_t cs_base_u32, int ch, int buf, int tid) {
    const char* srcs[3] = { (const char*)g_c0, (const char*)g_c1, (const char*)g_c2 };
    uint32_t dst_base = cs_base_u32 + (uint32_t)buf * 24576u;
    #pragma unroll
    for (int t = 0; t < 6; t++) {
        int j = tid + t * NTH;
        int split = j >> 9;
        int cand  = (j >> 3) & 63;
        int b     = j & 7;
        int bsw   = b ^ ((cand & 3) << 1);
        const char* src = srcs[split] + ((ch * CHC + cand) * D + b * 8) * 2;
        uint32_t dst = dst_base + (uint32_t)split * 8192u
                     + (uint32_t)cand * 128u + (uint32_t)bsw * 16u;
        CP_ASYNC16(dst, src);
    }
    CP_COMMIT();
}

// exact d2 in the R1-verified formula: sequential FFMA over d, then
// fadd(fmaf(-2, dot, xn), cn)
__device__ __forceinline__ float exact_d2(const float* __restrict__ cb,
                                          const float* xr, float xn,
                                          const float* cn_s, int idx) {
    const float4* cr = (const float4*)(cb + (long long)idx * D);
    float acc = 0.f;
    #pragma unroll
    for (int j = 0; j < 16; j++) {
        float4 c4 = cr[j];
        acc = __fmaf_rn(xr[4 * j + 0], c4.x, acc);
        acc = __fmaf_rn(xr[4 * j + 1], c4.y, acc);
        acc = __fmaf_rn(xr[4 * j + 2], c4.z, acc);
        acc = __fmaf_rn(xr[4 * j + 3], c4.w, acc);
    }
    return __fadd_rn(__fmaf_rn(-2.0f, acc, xn), cn_s[idx]);
}

// ---------------- main kernel ----------------
__global__ void __launch_bounds__(NTH, 1)
vq_main(const float* __restrict__ inp, const float* __restrict__ cb,
        float* __restrict__ out, int N, long long loss_off, long long idx_off) {
    extern __shared__ __align__(16) char sm[];
    const uint32_t sb = smem_u32(sm);

    const int tid = threadIdx.x;
    const int wid = tid >> 5;
    const int lane = tid & 31;
    const int g = lane >> 2;
    const int tig = lane & 3;
    const long long rowbase = (long long)blockIdx.x * MT;

    float* xf   = (float*)(sm + OFF_XF);
    float* cn_s = (float*)(sm + OFF_CN);
    float* xn_s = (float*)(sm + OFF_XN);
    int*   sidx = (int*)(sm + OFF_SIDX);
    float* sred = (float*)(sm + OFF_SRED);

    issue_chunk(sb + OFF_CS, 0, 0, tid);
    issue_chunk(sb + OFF_CS, 1, 1, tid);

    // ---- convert X: fp32 smem copy + 3-way bf16 permuted tiles ----
    const float* gx = inp + rowbase * D;
    #pragma unroll
    for (int i = 0; i < MT * D / NTH; i++) {
        int e = tid + i * NTH;
        int row = e >> 6, d = e & 63;
        float v = gx[e];
        xf[row * 65 + d] = v;
        __nv_bfloat16 h0 = __float2bfloat16_rn(v);
        float r1 = __fsub_rn(v, __bfloat162float(h0));
        __nv_bfloat16 h1 = __float2bfloat16_rn(r1);
        float r2 = __fsub_rn(r1, __bfloat162float(h1));
        __nv_bfloat16 h2 = __float2bfloat16_rn(r2);
        int ks = d >> 4, w16 = d & 15;
        int hi8 = w16 >> 3, tg = (w16 & 7) >> 1, sub = d & 1;
        int dw = 4 * ks + tg;
        int dws = dw ^ ((row & 3) << 2);
        int boff = row * 128 + dws * 8 + (hi8 * 2 + sub) * 2;
        *(__nv_bfloat16*)(sm + OFF_XB0 + boff) = h0;
        *(__nv_bfloat16*)(sm + OFF_XB1 + boff) = h1;
        *(__nv_bfloat16*)(sm + OFF_XB2 + boff) = h2;
    }
    #pragma unroll
    for (int i = 0; i < KCB / NTH; i++) cn_s[tid + i * NTH] = g_cnorm[tid + i * NTH];
    __syncthreads();

    {
        float s = 0.f;
        #pragma unroll
        for (int d = 0; d < D; d++) {
            float v = xf[tid * 65 + d];
            s = __fadd_rn(s, __fmul_rn(v, v));
        }
        xn_s[tid] = s;
    }
    __syncthreads();

    uint32_t dwo[4];
    #pragma unroll
    for (int ks = 0; ks < 4; ks++)
        dwo[ks] = (uint32_t)(((4 * ks + tig) ^ ((g & 3) << 2)) * 8);

    // ---- hoist A fragments (x0, x1, x2) ----
    uint32_t A0[2][4][4], A1[2][4][4], A2[2][4][4];
    const int r0 = wid * 32;
    #pragma unroll
    for (int at = 0; at < 2; at++) {
        int rlo = r0 + at * 16 + g;
        int rhi = rlo + 8;
        #pragma unroll
        for (int ks = 0; ks < 4; ks++) {
            LDS64(A0[at][ks][0], A0[at][ks][2], sb + OFF_XB0 + (uint32_t)rlo * 128u + dwo[ks]);
            LDS64(A0[at][ks][1], A0[at][ks][3], sb + OFF_XB0 + (uint32_t)rhi * 128u + dwo[ks]);
            LDS64(A1[at][ks][0], A1[at][ks][2], sb + OFF_XB1 + (uint32_t)rlo * 128u + dwo[ks]);
            LDS64(A1[at][ks][1], A1[at][ks][3], sb + OFF_XB1 + (uint32_t)rhi * 128u + dwo[ks]);
            LDS64(A2[at][ks][0], A2[at][ks][2], sb + OFF_XB2 + (uint32_t)rlo * 128u + dwo[ks]);
            LDS64(A2[at][ks][1], A2[at][ks][3], sb + OFF_XB2 + (uint32_t)rhi * 128u + dwo[ks]);
        }
    }

    float xn[4];
    #pragma unroll
    for (int s = 0; s < 4; s++)
        xn[s] = xn_s[r0 + (s >> 1) * 16 + ((s & 1) << 3) + g];

    // top-2 per (thread, row-slot): values + indices
    float bv1[4], bv2[4]; int bi1[4], bi2[4];
    #pragma unroll
    for (int s = 0; s < 4; s++) {
        bv1[s] = 3.4e38f; bv2[s] = 3.4e38f; bi1[s] = 0; bi2[s] = 0;
    }

    // ---- chunk loop ----
    for (int ch = 0; ch < NCH; ch++) {
        if (ch < 15) { asm volatile("cp.async.wait_group 1;" ::: "memory"); }
        else         { asm volatile("cp.async.wait_group 0;" ::: "memory"); }
        __syncthreads();

        const uint32_t cs0 = sb + OFF_CS + (uint32_t)(ch & 1) * 24576u;
        const uint32_t cs1 = cs0 + 8192u;
        const uint32_t cs2 = cs0 + 16384u;

        #pragma unroll
        for (int half = 0; half < 2; half++) {
            float acc[2][4][4];
            #pragma unroll
            for (int at = 0; at < 2; at++)
                #pragma unroll
                for (int nt = 0; nt < 4; nt++)
                    #pragma unroll
                    for (int q = 0; q < 4; q++) acc[at][nt][q] = 0.f;

            #pragma unroll
            for (int ks = 0; ks < 4; ks++) {
                uint32_t B0[4][2], B1[4][2], B2[4][2];
                #pragma unroll
                for (int nt = 0; nt < 4; nt++) {
                    const uint32_t crow = (uint32_t)((half * 4 + nt) * 8 + g) * 128u + dwo[ks];
                    LDS64(B0[nt][0], B0[nt][1], cs0 + crow);
                    LDS64(B1[nt][0], B1[nt][1], cs1 + crow);
                    LDS64(B2[nt][0], B2[nt][1], cs2 + crow);
                }
                #pragma unroll
                for (int at = 0; at < 2; at++)
                    #pragma unroll
                    for (int nt = 0; nt < 4; nt++)
                        MMA_BF16(acc[at][nt], A1[at][ks], B1[nt][0], B1[nt][1]);  // x1c1
                #pragma unroll
                for (int at = 0; at < 2; at++)
                    #pragma unroll
                    for (int nt = 0; nt < 4; nt++)
                        MMA_BF16(acc[at][nt], A0[at][ks], B2[nt][0], B2[nt][1]);  // x0c2
                #pragma unroll
                for (int at = 0; at < 2; at++)
                    #pragma unroll
                    for (int nt = 0; nt < 4; nt++)
                        MMA_BF16(acc[at][nt], A2[at][ks], B0[nt][0], B0[nt][1]);  // x2c0
                #pragma unroll
                for (int at = 0; at < 2; at++)
                    #pragma unroll
                    for (int nt = 0; nt < 4; nt++)
                        MMA_BF16(acc[at][nt], A0[at][ks], B1[nt][0], B1[nt][1]);  // x0c1
                #pragma unroll
                for (int at = 0; at < 2; at++)
                    #pragma unroll
                    for (int nt = 0; nt < 4; nt++)
                        MMA_BF16(acc[at][nt], A1[at][ks], B0[nt][0], B0[nt][1]);  // x1c0
                #pragma unroll
                for (int at = 0; at < 2; at++)
                    #pragma unroll
                    for (int nt = 0; nt < 4; nt++)
                        MMA_BF16(acc[at][nt], A0[at][ks], B0[nt][0], B0[nt][1]);  // x0c0
            }

            // ---- epilogue: d2 + top-2 tracking (strict <, index order preserved) ----
            #pragma unroll
            for (int nt = 0; nt < 4; nt++) {
                const int c2 = ch * CHC + (half * 4 + nt) * 8 + 2 * tig;
                const float cn0 = cn_s[c2];
                const float cn1 = cn_s[c2 + 1];
                #pragma unroll
                for (int at = 0; at < 2; at++) {
                    #pragma unroll
                    for (int sub = 0; sub < 2; sub++) {
                        const int s = at * 2 + sub;
                        float t0 = __fadd_rn(__fmaf_rn(-2.0f, acc[at][nt][sub * 2 + 0], xn[s]), cn0);
                        if (t0 < bv1[s]) { bv2[s] = bv1[s]; bi2[s] = bi1[s]; bv1[s] = t0; bi1[s] = c2; }
                        else if (t0 < bv2[s]) { bv2[s] = t0; bi2[s] = c2; }
                        float t1 = __fadd_rn(__fmaf_rn(-2.0f, acc[at][nt][sub * 2 + 1], xn[s]), cn1);
                        if (t1 < bv1[s]) { bv2[s] = bv1[s]; bi2[s] = bi1[s]; bv1[s] = t1; bi1[s] = c2 + 1; }
                        else if (t1 < bv2[s]) { bv2[s] = t1; bi2[s] = c2 + 1; }
                    }
                }
            }
        }

        __syncthreads();
        if (ch + 2 < NCH) issue_chunk(sb + OFF_CS, ch + 2, ch & 1, tid);
    }

    // ---- exact rescore of per-lane top-2, then cross-lane exact argmin ----
    #pragma unroll
    for (int s = 0; s < 4; s++) {
        int row = r0 + (s >> 1) * 16 + ((s & 1) << 3) + g;
        const float* xr = xf + row * 65;
        float e1 = exact_d2(cb, xr, xn[s], cn_s, bi1[s]);
        float e2 = exact_d2(cb, xr, xn[s], cn_s, bi2[s]);
        float wv = e1; int wi = bi1[s];
        if (e2 < wv || (e2 == wv && bi2[s] < wi)) { wv = e2; wi = bi2[s]; }
        #pragma unroll
        for (int off = 1; off < 4; off <<= 1) {
            float ov = __shfl_xor_sync(0xffffffffu, wv, off);
            int   oi = __shfl_xor_sync(0xffffffffu, wi, off);
            if (ov < wv || (ov == wv && oi < wi)) { wv = ov; wi = oi; }
        }
        if (tig == 0) sidx[row] = wi;
    }
    __syncthreads();

    // ---- writeback: quantized_ste + loss partial ----
    float lsum = 0.f;
    #pragma unroll
    for (int i = 0; i < MT * D / NTH; i++) {
        int e = tid + i * NTH;
        int row = e >> 6, d = e & 63;
        int idx = sidx[row];
        float x = xf[row * 65 + d];
        float q = cb[(long long)idx * D + d];
        float diff = __fsub_rn(q, x);
        out[rowbase * D + e] = __fadd_rn(x, diff);
        lsum = __fmaf_rn(diff, diff, lsum);
    }
    if (idx_off >= 0) out[idx_off + rowbase + tid] = (float)sidx[tid];

    #pragma unroll
    for (int off = 16; off; off >>= 1)
        lsum += __shfl_xor_sync(0xffffffffu, lsum, off);
    if (lane == 0) sred[wid] = lsum;
    __syncthreads();
    if (tid == 0) {
        float s = 0.f;
        #pragma unroll
        for (int w = 0; w < NTH / 32; w++) s += sred[w];
        g_part[blockIdx.x] = s;
    }
}

__global__ void vq_final(float* __restrict__ out, int nb,
                         long long loss_off, double inv_cnt) {
    __shared__ double sd[256];
    double s = 0.0;
    for (int i = threadIdx.x; i < nb; i += blockDim.x) s += (double)g_part[i];
    sd[threadIdx.x] = s;
    __syncthreads();
    for (int k = 128; k; k >>= 1) {
        if (threadIdx.x < k) sd[threadIdx.x] += sd[threadIdx.x + k];
        __syncthreads();
    }
    if (threadIdx.x == 0) {
        float m = (float)(sd[0] * inv_cnt);
        out[loss_off] = __fadd_rn(m, __fmul_rn(0.25f, m));
    }
}

extern "C" void kernel_launch(void* const* d_in, const int* in_sizes, int n_in,
                              void* d_out, int out_size) {
    const float* inp = (const float*)d_in[0];
    const float* cb  = (const float*)d_in[1];
    float* out = (float*)d_out;

    const int N = in_sizes[0] / D;                 // 131072
    const long long sq = (long long)N * D;
    long long loss_off = -1, idx_off = -1;
    if ((long long)out_size >= sq + 1)     loss_off = sq;
    if ((long long)out_size >= sq + 1 + N) idx_off  = sq + 1;

    const int nb = N / MT;                         // 512

    cudaFuncSetAttribute(vq_main, cudaFuncAttributeMaxDynamicSharedMemorySize, SMEM_DYN);

    vq_prep<<<(KCB + 255) / 256, 256>>>(cb);
    vq_main<<<nb, NTH, SMEM_DYN>>>(inp, cb, out, N, loss_off, idx_off);
    if (loss_off >= 0)
        vq_final<<<1, 256>>>(out, nb, loss_off, 1.0 / (double)((long long)N * D));
}

// round 6
// speedup vs baseline: 1.4357x; 1.0794x over previous
#include <cuda_runtime.h>
#include <cuda_bf16.h>
#include <stdint.h>

#define D     64
#define KCB   1024
#define MT    256          // rows per block
#define NTH   256          // 8 warps
#define CHC   64           // candidates per chunk
#define NCH   (KCB/CHC)    // 16

// ---------------- device globals ----------------
__device__ __align__(16) __nv_bfloat16 g_c0[KCB * D];   // permuted bf16 split 0
__device__ __align__(16) __nv_bfloat16 g_c1[KCB * D];   // split 1
__device__ float g_cnorm[KCB];
__device__ float g_part[1024];

// ---------------- smem layout (bytes) ----------------
#define OFF_XB0   0                       // bf16 x0, 256 rows * 128B
#define OFF_XB1   32768                   // bf16 x1
#define OFF_CS    65536                   // 2 bufs * (c0 8KB | c1 8KB) = 32KB
#define OFF_CN    98304                   // 1024 f32
#define OFF_XN    102400                  // 256 f32
#define OFF_SIDX  103424                  // 256 i32
#define OFF_SRED  104448                  // 8 f32
#define SMEM_DYN  104480

__device__ __forceinline__ uint32_t smem_u32(const void* p) {
    uint32_t a;
    asm("{ .reg .u64 t; cvta.to.shared.u64 t, %1; cvt.u32.u64 %0, t; }"
        : "=r"(a) : "l"(p));
    return a;
}

#define LDS64(r0_, r1_, a) \
    asm volatile("ld.shared.v2.b32 {%0,%1}, [%2];" : "=r"(r0_), "=r"(r1_) : "r"(a))

#define MMA_BF16(dd, aa, b0_, b1_) \
    asm volatile("mma.sync.aligned.m16n8k16.row.col.f32.bf16.bf16.f32 " \
        "{%0,%1,%2,%3}, {%4,%5,%6,%7}, {%8,%9}, {%0,%1,%2,%3};" \
        : "+f"((dd)[0]), "+f"((dd)[1]), "+f"((dd)[2]), "+f"((dd)[3]) \
        : "r"((aa)[0]), "r"((aa)[1]), "r"((aa)[2]), "r"((aa)[3]), \
          "r"(b0_), "r"(b1_))

#define CP_ASYNC16(dst, src) \
    asm volatile("cp.async.cg.shared.global [%0], [%1], 16;" \
                 :: "r"(dst), "l"(src) : "memory")
#define CP_COMMIT() asm volatile("cp.async.commit_group;" ::: "memory")

// ---------------- prep: 2-way bf16 split (permuted, parallel) + exact cnorm ----
// dword dw = 4*ks + tig holds bf16 elements d = {16ks+2tig, +1, 16ks+2tig+8, +9}
__global__ void vq_prep(const float* __restrict__ cb) {
    int i = blockIdx.x * blockDim.x + threadIdx.x;
    if (i < KCB * D) {
        int k = i >> 6, d = i & 63;
        float v = cb[i];
        __nv_bfloat16 h0 = __float2bfloat16_rn(v);
        float r1 = __fsub_rn(v, __bfloat162float(h0));
        __nv_bfloat16 h1 = __float2bfloat16_rn(r1);
        int ks = d >> 4, w16 = d & 15;
        int hi8 = w16 >> 3, tig = (w16 & 7) >> 1, sub = d & 1;
        int pos = (4 * ks + tig) * 4 + hi8 * 2 + sub;
        g_c0[k * D + pos] = h0;
        g_c1[k * D + pos] = h1;
    }
    if (i < KCB) {
        float s = 0.f;
        #pragma unroll
        for (int d = 0; d < D; d++) {
            float v = cb[i * D + d];
            s = __fadd_rn(s, __fmul_rn(v, v));
        }
        g_cnorm[i] = s;
    }
}

// issue async copy of chunk ch into buffer buf (256 threads, 4x16B each = 16KB)
__device__ __forceinline__ void issue_chunk(uint32_t cs_base_u32, int ch, int buf, int tid) {
    uint32_t dst_base = cs_base_u32 + (uint32_t)buf * 16384u;
    #pragma unroll
    for (int t = 0; t < 4; t++) {
        int j = tid + t * NTH;           // 0..1023
        int split = j >> 9;              // 0/1
        int cand  = (j >> 3) & 63;
        int b     = j & 7;
        int bsw   = b ^ ((cand & 3) << 1);
        const char* src = (const char*)(split ? g_c1 : g_c0)
                        + ((ch * CHC + cand) * D + b * 8) * 2;
        uint32_t dst = dst_base + (uint32_t)split * 8192u
                     + (uint32_t)cand * 128u + (uint32_t)bsw * 16u;
        CP_ASYNC16(dst, src);
    }
    CP_COMMIT();
}

// exact d2 in the R1-verified formula: sequential FFMA over d, then
// fadd(fmaf(-2, dot, xn), cn)  (x and c read from global, L2-hot)
__device__ __forceinline__ float exact_d2(const float* __restrict__ cb,
                                          const float* __restrict__ xr, float xn,
                                          const float* cn_s, int idx) {
    const float4* cr = (const float4*)(cb + (long long)idx * D);
    const float4* xr4 = (const float4*)xr;
    float acc = 0.f;
    #pragma unroll
    for (int j = 0; j < 16; j++) {
        float4 c4 = cr[j];
        float4 x4 = xr4[j];
        acc = __fmaf_rn(x4.x, c4.x, acc);
        acc = __fmaf_rn(x4.y, c4.y, acc);
        acc = __fmaf_rn(x4.z, c4.z, acc);
        acc = __fmaf_rn(x4.w, c4.w, acc);
    }
    return __fadd_rn(__fmaf_rn(-2.0f, acc, xn), cn_s[idx]);
}

// ---------------- main kernel ----------------
__global__ void __launch_bounds__(NTH, 2)
vq_main(const float* __restrict__ inp, const float* __restrict__ cb,
        float* __restrict__ out, int N, long long loss_off, long long idx_off) {
    extern __shared__ __align__(16) char sm[];
    const uint32_t sb = smem_u32(sm);

    const int tid = threadIdx.x;
    const int wid = tid >> 5;
    const int lane = tid & 31;
    const int g = lane >> 2;
    const int tig = lane & 3;
    const long long rowbase = (long long)blockIdx.x * MT;

    float* cn_s = (float*)(sm + OFF_CN);
    float* xn_s = (float*)(sm + OFF_XN);
    int*   sidx = (int*)(sm + OFF_SIDX);
    float* sred = (float*)(sm + OFF_SRED);

    issue_chunk(sb + OFF_CS, 0, 0, tid);
    issue_chunk(sb + OFF_CS, 1, 1, tid);

    // ---- convert X: 2-way bf16 permuted tiles (x reloaded from gmem later) ----
    const float* gx = inp + rowbase * D;
    #pragma unroll
    for (int i = 0; i < MT * D / NTH; i++) {
        int e = tid + i * NTH;
        int row = e >> 6, d = e & 63;
        float v = gx[e];
        __nv_bfloat16 h0 = __float2bfloat16_rn(v);
        float r1 = __fsub_rn(v, __bfloat162float(h0));
        __nv_bfloat16 h1 = __float2bfloat16_rn(r1);
        int ks = d >> 4, w16 = d & 15;
        int hi8 = w16 >> 3, tg = (w16 & 7) >> 1, sub = d & 1;
        int dw = 4 * ks + tg;
        int dws = dw ^ ((row & 3) << 2);
        int boff = row * 128 + dws * 8 + (hi8 * 2 + sub) * 2;
        *(__nv_bfloat16*)(sm + OFF_XB0 + boff) = h0;
        *(__nv_bfloat16*)(sm + OFF_XB1 + boff) = h1;
    }
    #pragma unroll
    for (int i = 0; i < KCB / NTH; i++) cn_s[tid + i * NTH] = g_cnorm[tid + i * NTH];

    // per-row exact xnorm from global (sequential mul-add, matches reference)
    {
        float s = 0.f;
        const float* xr = gx + tid * D;
        #pragma unroll
        for (int d = 0; d < D; d++) {
            float v = xr[d];
            s = __fadd_rn(s, __fmul_rn(v, v));
        }
        xn_s[tid] = s;
    }
    __syncthreads();

    uint32_t dwo[4];
    #pragma unroll
    for (int ks = 0; ks < 4; ks++)
        dwo[ks] = (uint32_t)(((4 * ks + tig) ^ ((g & 3) << 2)) * 8);

    const int r0 = wid * 32;
    float xn[4];
    #pragma unroll
    for (int s = 0; s < 4; s++)
        xn[s] = xn_s[r0 + (s >> 1) * 16 + ((s & 1) << 3) + g];

    // top-2 per (thread, row-slot)
    float bv1[4], bv2[4]; int bi1[4], bi2[4];
    #pragma unroll
    for (int s = 0; s < 4; s++) {
        bv1[s] = 3.4e38f; bv2[s] = 3.4e38f; bi1[s] = 0; bi2[s] = 0;
    }

    // ---- chunk loop ----
    for (int ch = 0; ch < NCH; ch++) {
        if (ch < 15) { asm volatile("cp.async.wait_group 1;" ::: "memory"); }
        else         { asm volatile("cp.async.wait_group 0;" ::: "memory"); }
        __syncthreads();

        const uint32_t cs0 = sb + OFF_CS + (uint32_t)(ch & 1) * 16384u;
        const uint32_t cs1 = cs0 + 8192u;

        #pragma unroll
        for (int half = 0; half < 2; half++) {
            float acc[2][4][4];
            #pragma unroll
            for (int at = 0; at < 2; at++)
                #pragma unroll
                for (int nt = 0; nt < 4; nt++)
                    #pragma unroll
                    for (int q = 0; q < 4; q++) acc[at][nt][q] = 0.f;

            #pragma unroll
            for (int ks = 0; ks < 4; ks++) {
                // A fragments for this ks (x0, x1)
                uint32_t a0[2][4], a1[2][4];
                #pragma unroll
                for (int at = 0; at < 2; at++) {
                    uint32_t rlo = (uint32_t)(r0 + at * 16 + g) * 128u + dwo[ks];
                    uint32_t rhi = rlo + 8u * 128u;
                    LDS64(a0[at][0], a0[at][2], sb + OFF_XB0 + rlo);
                    LDS64(a0[at][1], a0[at][3], sb + OFF_XB0 + rhi);
                    LDS64(a1[at][0], a1[at][2], sb + OFF_XB1 + rlo);
                    LDS64(a1[at][1], a1[at][3], sb + OFF_XB1 + rhi);
                }
                // B fragments
                uint32_t B0[4][2], B1[4][2];
                #pragma unroll
                for (int nt = 0; nt < 4; nt++) {
                    const uint32_t crow = (uint32_t)((half * 4 + nt) * 8 + g) * 128u + dwo[ks];
                    LDS64(B0[nt][0], B0[nt][1], cs0 + crow);
                    LDS64(B1[nt][0], B1[nt][1], cs1 + crow);
                }
                // small terms first, then dominant
                #pragma unroll
                for (int at = 0; at < 2; at++)
                    #pragma unroll
                    for (int nt = 0; nt < 4; nt++)
                        MMA_BF16(acc[at][nt], a0[at], B1[nt][0], B1[nt][1]);  // x0c1
                #pragma unroll
                for (int at = 0; at < 2; at++)
                    #pragma unroll
                    for (int nt = 0; nt < 4; nt++)
                        MMA_BF16(acc[at][nt], a1[at], B0[nt][0], B0[nt][1]);  // x1c0
                #pragma unroll
                for (int at = 0; at < 2; at++)
                    #pragma unroll
                    for (int nt = 0; nt < 4; nt++)
                        MMA_BF16(acc[at][nt], a0[at], B0[nt][0], B0[nt][1]);  // x0c0
            }

            // ---- epilogue: d2 + top-2 tracking ----
            #pragma unroll
            for (int nt = 0; nt < 4; nt++) {
                const int c2 = ch * CHC + (half * 4 + nt) * 8 + 2 * tig;
                const float cn0 = cn_s[c2];
                const float cn1 = cn_s[c2 + 1];
                #pragma unroll
                for (int at = 0; at < 2; at++) {
                    #pragma unroll
                    for (int sub = 0; sub < 2; sub++) {
                        const int s = at * 2 + sub;
                        float t0 = __fadd_rn(__fmaf_rn(-2.0f, acc[at][nt][sub * 2 + 0], xn[s]), cn0);
                        if (t0 < bv1[s]) { bv2[s] = bv1[s]; bi2[s] = bi1[s]; bv1[s] = t0; bi1[s] = c2; }
                        else if (t0 < bv2[s]) { bv2[s] = t0; bi2[s] = c2; }
                        float t1 = __fadd_rn(__fmaf_rn(-2.0f, acc[at][nt][sub * 2 + 1], xn[s]), cn1);
                        if (t1 < bv1[s]) { bv2[s] = bv1[s]; bi2[s] = bi1[s]; bv1[s] = t1; bi1[s] = c2 + 1; }
                        else if (t1 < bv2[s]) { bv2[s] = t1; bi2[s] = c2 + 1; }
                    }
                }
            }
        }

        __syncthreads();
        if (ch + 2 < NCH) issue_chunk(sb + OFF_CS, ch + 2, ch & 1, tid);
    }

    // ---- exact rescore of per-lane top-2, then cross-lane exact argmin ----
    #pragma unroll
    for (int s = 0; s < 4; s++) {
        int row = r0 + (s >> 1) * 16 + ((s & 1) << 3) + g;
        const float* xr = gx + row * D;
        float e1 = exact_d2(cb, xr, xn[s], cn_s, bi1[s]);
        float e2 = exact_d2(cb, xr, xn[s], cn_s, bi2[s]);
        float wv = e1; int wi = bi1[s];
        if (e2 < wv || (e2 == wv && bi2[s] < wi)) { wv = e2; wi = bi2[s]; }
        #pragma unroll
        for (int off = 1; off < 4; off <<= 1) {
            float ov = __shfl_xor_sync(0xffffffffu, wv, off);
            int   oi = __shfl_xor_sync(0xffffffffu, wi, off);
            if (ov < wv || (ov == wv && oi < wi)) { wv = ov; wi = oi; }
        }
        if (tig == 0) sidx[row] = wi;
    }
    __syncthreads();

    // ---- writeback: quantized_ste + loss partial (x reloaded, L2-hot) ----
    float lsum = 0.f;
    #pragma unroll
    for (int i = 0; i < MT * D / NTH; i++) {
        int e = tid + i * NTH;
        int row = e >> 6, d = e & 63;
        int idx = sidx[row];
        float x = gx[e];
        float q = cb[(long long)idx * D + d];
        float diff = __fsub_rn(q, x);
        out[rowbase * D + e] = __fadd_rn(x, diff);
        lsum = __fmaf_rn(diff, diff, lsum);
    }
    if (idx_off >= 0) out[idx_off + rowbase + tid] = (float)sidx[tid];

    #pragma unroll
    for (int off = 16; off; off >>= 1)
        lsum += __shfl_xor_sync(0xffffffffu, lsum, off);
    if (lane == 0) sred[wid] = lsum;
    __syncthreads();
    if (tid == 0) {
        float s = 0.f;
        #pragma unroll
        for (int w = 0; w < NTH / 32; w++) s += sred[w];
        g_part[blockIdx.x] = s;
    }
}

__global__ void vq_final(float* __restrict__ out, int nb,
                         long long loss_off, double inv_cnt) {
    __shared__ double sd[256];
    double s = 0.0;
    for (int i = threadIdx.x; i < nb; i += blockDim.x) s += (double)g_part[i];
    sd[threadIdx.x] = s;
    __syncthreads();
    for (int k = 128; k; k >>= 1) {
        if (threadIdx.x < k) sd[threadIdx.x] += sd[threadIdx.x + k];
        __syncthreads();
    }
    if (threadIdx.x == 0) {
        float m = (float)(sd[0] * inv_cnt);
        out[loss_off] = __fadd_rn(m, __fmul_rn(0.25f, m));
    }
}

extern "C" void kernel_launch(void* const* d_in, const int* in_sizes, int n_in,
                              void* d_out, int out_size) {
    const float* inp = (const float*)d_in[0];
    const float* cb  = (const float*)d_in[1];
    float* out = (float*)d_out;

    const int N = in_sizes[0] / D;                 // 131072
    const long long sq = (long long)N * D;
    long long loss_off = -1, idx_off = -1;
    if ((long long)out_size >= sq + 1)     loss_off = sq;
    if ((long long)out_size >= sq + 1 + N) idx_off  = sq + 1;

    const int nb = N / MT;                         // 512

    cudaFuncSetAttribute(vq_main, cudaFuncAttributeMaxDynamicSharedMemorySize, SMEM_DYN);

    vq_prep<<<(KCB * D + 255) / 256, 256>>>(cb);
    vq_main<<<nb, NTH, SMEM_DYN>>>(inp, cb, out, N, loss_off, idx_off);
    if (loss_off >= 0)
        vq_final<<<1, 256>>>(out, nb, loss_off, 1.0 / (double)((long long)N * D));
}

// round 7
// speedup vs baseline: 1.7416x; 1.2131x over previous
#include <cuda_runtime.h>
#include <cuda_bf16.h>
#include <stdint.h>

#define D     64
#define KCB   1024
#define MT    256          // rows per block
#define NTH   256          // 8 warps
#define CHC   64           // candidates per chunk
#define NCH   (KCB/CHC)    // 16

// ---------------- device globals ----------------
__device__ __align__(16) __nv_bfloat16 g_c0[KCB * D];   // permuted bf16 split 0
__device__ __align__(16) __nv_bfloat16 g_c1[KCB * D];   // split 1
__device__ float g_cnorm[KCB];
__device__ float g_part[1024];

// ---------------- smem layout (bytes) ----------------
#define OFF_XB0   0                       // bf16 x0, 256 rows * 128B
#define OFF_XB1   32768                   // bf16 x1
#define OFF_CS    65536                   // 2 bufs * (c0 8KB | c1 8KB) = 32KB
#define OFF_CN    98304                   // 1024 f32 (exact cnorm, for rescore)
#define OFF_CN2   102400                  // 1024 f32 (cnorm/2, for screening)
#define OFF_XN    106496                  // 256 f32
#define OFF_SIDX  107520                  // 256 i32
#define OFF_SRED  108544                  // 8 f32
#define SMEM_DYN  108576

__device__ __forceinline__ uint32_t smem_u32(const void* p) {
    uint32_t a;
    asm("{ .reg .u64 t; cvta.to.shared.u64 t, %1; cvt.u32.u64 %0, t; }"
        : "=r"(a) : "l"(p));
    return a;
}

// NOTE: non-volatile — let ptxas hoist/pipeline these
#define LDS64(r0_, r1_, a) \
    asm("ld.shared.v2.b32 {%0,%1}, [%2];" : "=r"(r0_), "=r"(r1_) : "r"(a))

#define MMA_BF16(dd, aa, b0_, b1_) \
    asm("mma.sync.aligned.m16n8k16.row.col.f32.bf16.bf16.f32 " \
        "{%0,%1,%2,%3}, {%4,%5,%6,%7}, {%8,%9}, {%0,%1,%2,%3};" \
        : "+f"((dd)[0]), "+f"((dd)[1]), "+f"((dd)[2]), "+f"((dd)[3]) \
        : "r"((aa)[0]), "r"((aa)[1]), "r"((aa)[2]), "r"((aa)[3]), \
          "r"(b0_), "r"(b1_))

#define CP_ASYNC16(dst, src) \
    asm volatile("cp.async.cg.shared.global [%0], [%1], 16;" \
                 :: "r"(dst), "l"(src) : "memory")
#define CP_COMMIT() asm volatile("cp.async.commit_group;" ::: "memory")

// ---------------- prep: 2-way bf16 split (permuted, parallel) + exact cnorm ----
__global__ void vq_prep(const float* __restrict__ cb) {
    int i = blockIdx.x * blockDim.x + threadIdx.x;
    if (i < KCB * D) {
        int k = i >> 6, d = i & 63;
        float v = cb[i];
        __nv_bfloat16 h0 = __float2bfloat16_rn(v);
        float r1 = __fsub_rn(v, __bfloat162float(h0));
        __nv_bfloat16 h1 = __float2bfloat16_rn(r1);
        int ks = d >> 4, w16 = d & 15;
        int hi8 = w16 >> 3, tig = (w16 & 7) >> 1, sub = d & 1;
        int pos = (4 * ks + tig) * 4 + hi8 * 2 + sub;
        g_c0[k * D + pos] = h0;
        g_c1[k * D + pos] = h1;
    }
    if (i < KCB) {
        float s = 0.f;
        #pragma unroll
        for (int d = 0; d < D; d++) {
            float v = cb[i * D + d];
            s = __fadd_rn(s, __fmul_rn(v, v));
        }
        g_cnorm[i] = s;
    }
}

// issue async copy of chunk ch into buffer buf
__device__ __forceinline__ void issue_chunk(uint32_t cs_base_u32, int ch, int buf, int tid) {
    uint32_t dst_base = cs_base_u32 + (uint32_t)buf * 16384u;
    #pragma unroll
    for (int t = 0; t < 4; t++) {
        int j = tid + t * NTH;
        int split = j >> 9;
        int cand  = (j >> 3) & 63;
        int b     = j & 7;
        int bsw   = b ^ ((cand & 3) << 1);
        const char* src = (const char*)(split ? g_c1 : g_c0)
                        + ((ch * CHC + cand) * D + b * 8) * 2;
        uint32_t dst = dst_base + (uint32_t)split * 8192u
                     + (uint32_t)cand * 128u + (uint32_t)bsw * 16u;
        CP_ASYNC16(dst, src);
    }
    CP_COMMIT();
}

// exact d2 in the R1-verified formula (bit-matching the reference rounding)
__device__ __forceinline__ float exact_d2(const float* __restrict__ cb,
                                          const float* __restrict__ xr, float xn,
                                          const float* cn_s, int idx) {
    const float4* cr = (const float4*)(cb + (long long)idx * D);
    const float4* xr4 = (const float4*)xr;
    float acc = 0.f;
    #pragma unroll
    for (int j = 0; j < 16; j++) {
        float4 c4 = cr[j];
        float4 x4 = xr4[j];
        acc = __fmaf_rn(x4.x, c4.x, acc);
        acc = __fmaf_rn(x4.y, c4.y, acc);
        acc = __fmaf_rn(x4.z, c4.z, acc);
        acc = __fmaf_rn(x4.w, c4.w, acc);
    }
    return __fadd_rn(__fmaf_rn(-2.0f, acc, xn), cn_s[idx]);
}

// ---------------- main kernel ----------------
__global__ void __launch_bounds__(NTH, 2)
vq_main(const float* __restrict__ inp, const float* __restrict__ cb,
        float* __restrict__ out, int N, long long loss_off, long long idx_off) {
    extern __shared__ __align__(16) char sm[];
    const uint32_t sb = smem_u32(sm);

    const int tid = threadIdx.x;
    const int wid = tid >> 5;
    const int lane = tid & 31;
    const int g = lane >> 2;
    const int tig = lane & 3;
    const long long rowbase = (long long)blockIdx.x * MT;

    float* cn_s  = (float*)(sm + OFF_CN);
    float* cn2_s = (float*)(sm + OFF_CN2);
    float* xn_s  = (float*)(sm + OFF_XN);
    int*   sidx  = (int*)(sm + OFF_SIDX);
    float* sred  = (float*)(sm + OFF_SRED);

    issue_chunk(sb + OFF_CS, 0, 0, tid);
    issue_chunk(sb + OFF_CS, 1, 1, tid);

    // ---- convert X: 2-way bf16 permuted tiles ----
    const float* gx = inp + rowbase * D;
    #pragma unroll
    for (int i = 0; i < MT * D / NTH; i++) {
        int e = tid + i * NTH;
        int row = e >> 6, d = e & 63;
        float v = gx[e];
        __nv_bfloat16 h0 = __float2bfloat16_rn(v);
        float r1 = __fsub_rn(v, __bfloat162float(h0));
        __nv_bfloat16 h1 = __float2bfloat16_rn(r1);
        int ks = d >> 4, w16 = d & 15;
        int hi8 = w16 >> 3, tg = (w16 & 7) >> 1, sub = d & 1;
        int dw = 4 * ks + tg;
        int dws = dw ^ ((row & 3) << 2);
        int boff = row * 128 + dws * 8 + (hi8 * 2 + sub) * 2;
        *(__nv_bfloat16*)(sm + OFF_XB0 + boff) = h0;
        *(__nv_bfloat16*)(sm + OFF_XB1 + boff) = h1;
    }
    #pragma unroll
    for (int i = 0; i < KCB / NTH; i++) {
        float c = g_cnorm[tid + i * NTH];
        cn_s[tid + i * NTH]  = c;
        cn2_s[tid + i * NTH] = __fmul_rn(c, 0.5f);
    }

    // per-row exact xnorm (sequential mul-add, matches reference)
    {
        float s = 0.f;
        const float* xr = gx + tid * D;
        #pragma unroll
        for (int d = 0; d < D; d++) {
            float v = xr[d];
            s = __fadd_rn(s, __fmul_rn(v, v));
        }
        xn_s[tid] = s;
    }
    __syncthreads();

    uint32_t dwo[4];
    #pragma unroll
    for (int ks = 0; ks < 4; ks++)
        dwo[ks] = (uint32_t)(((4 * ks + tig) ^ ((g & 3) << 2)) * 8);

    const int r0 = wid * 32;

    // top-2 (maximize y = dot - cn/2) per (thread, row-slot)
    float bv1[4], bv2[4]; int bi1[4], bi2[4];
    #pragma unroll
    for (int s = 0; s < 4; s++) {
        bv1[s] = -3.4e38f; bv2[s] = -3.4e38f; bi1[s] = 0; bi2[s] = 0;
    }

    // ---- chunk loop ----
    for (int ch = 0; ch < NCH; ch++) {
        if (ch < 15) { asm volatile("cp.async.wait_group 1;" ::: "memory"); }
        else         { asm volatile("cp.async.wait_group 0;" ::: "memory"); }
        __syncthreads();

        const uint32_t cs0 = sb + OFF_CS + (uint32_t)(ch & 1) * 16384u;
        const uint32_t cs1 = cs0 + 8192u;

        #pragma unroll
        for (int pass = 0; pass < 4; pass++) {
            float acc[2][2][4];
            #pragma unroll
            for (int at = 0; at < 2; at++)
                #pragma unroll
                for (int nt = 0; nt < 2; nt++)
                    #pragma unroll
                    for (int q = 0; q < 4; q++) acc[at][nt][q] = 0.f;

            #pragma unroll
            for (int ks = 0; ks < 4; ks++) {
                uint32_t a0[2][4], a1[2][4];
                #pragma unroll
                for (int at = 0; at < 2; at++) {
                    uint32_t rlo = (uint32_t)(r0 + at * 16 + g) * 128u + dwo[ks];
                    uint32_t rhi = rlo + 8u * 128u;
                    LDS64(a0[at][0], a0[at][2], sb + OFF_XB0 + rlo);
                    LDS64(a0[at][1], a0[at][3], sb + OFF_XB0 + rhi);
                    LDS64(a1[at][0], a1[at][2], sb + OFF_XB1 + rlo);
                    LDS64(a1[at][1], a1[at][3], sb + OFF_XB1 + rhi);
                }
                uint32_t B0[2][2], B1[2][2];
                #pragma unroll
                for (int nt = 0; nt < 2; nt++) {
                    const uint32_t crow =
                        (uint32_t)((pass * 2 + nt) * 8 + g) * 128u + dwo[ks];
                    LDS64(B0[nt][0], B0[nt][1], cs0 + crow);
                    LDS64(B1[nt][0], B1[nt][1], cs1 + crow);
                }
                // small terms first, then dominant
                #pragma unroll
                for (int at = 0; at < 2; at++)
                    #pragma unroll
                    for (int nt = 0; nt < 2; nt++)
                        MMA_BF16(acc[at][nt], a0[at], B1[nt][0], B1[nt][1]);  // x0c1
                #pragma unroll
                for (int at = 0; at < 2; at++)
                    #pragma unroll
                    for (int nt = 0; nt < 2; nt++)
                        MMA_BF16(acc[at][nt], a1[at], B0[nt][0], B0[nt][1]);  // x1c0
                #pragma unroll
                for (int at = 0; at < 2; at++)
                    #pragma unroll
                    for (int nt = 0; nt < 2; nt++)
                        MMA_BF16(acc[at][nt], a0[at], B0[nt][0], B0[nt][1]);  // x0c0
            }

            // ---- epilogue: y = dot - cn/2, top-2 max tracking ----
            #pragma unroll
            for (int nt = 0; nt < 2; nt++) {
                const int c2 = ch * CHC + (pass * 2 + nt) * 8 + 2 * tig;
                const float cn0 = cn2_s[c2];
                const float cn1 = cn2_s[c2 + 1];
                #pragma unroll
                for (int at = 0; at < 2; at++) {
                    #pragma unroll
                    for (int sub = 0; sub < 2; sub++) {
                        const int s = at * 2 + sub;
                        float t0 = __fsub_rn(acc[at][nt][sub * 2 + 0], cn0);
                        if (t0 > bv1[s]) { bv2[s] = bv1[s]; bi2[s] = bi1[s]; bv1[s] = t0; bi1[s] = c2; }
                        else if (t0 > bv2[s]) { bv2[s] = t0; bi2[s] = c2; }
                        float t1 = __fsub_rn(acc[at][nt][sub * 2 + 1], cn1);
                        if (t1 > bv1[s]) { bv2[s] = bv1[s]; bi2[s] = bi1[s]; bv1[s] = t1; bi1[s] = c2 + 1; }
                        else if (t1 > bv2[s]) { bv2[s] = t1; bi2[s] = c2 + 1; }
                    }
                }
            }
        }

        __syncthreads();
        if (ch + 2 < NCH) issue_chunk(sb + OFF_CS, ch + 2, ch & 1, tid);
    }

    // ---- exact rescore of per-lane top-2, then cross-lane exact argmin ----
    #pragma unroll
    for (int s = 0; s < 4; s++) {
        int row = r0 + (s >> 1) * 16 + ((s & 1) << 3) + g;
        const float* xr = gx + row * D;
        float xnv = xn_s[row];
        float e1 = exact_d2(cb, xr, xnv, cn_s, bi1[s]);
        float e2 = exact_d2(cb, xr, xnv, cn_s, bi2[s]);
        float wv = e1; int wi = bi1[s];
        if (e2 < wv || (e2 == wv && bi2[s] < wi)) { wv = e2; wi = bi2[s]; }
        #pragma unroll
        for (int off = 1; off < 4; off <<= 1) {
            float ov = __shfl_xor_sync(0xffffffffu, wv, off);
            int   oi = __shfl_xor_sync(0xffffffffu, wi, off);
            if (ov < wv || (ov == wv && oi < wi)) { wv = ov; wi = oi; }
        }
        if (tig == 0) sidx[row] = wi;
    }
    __syncthreads();

    // ---- writeback: quantized_ste + loss partial ----
    float lsum = 0.f;
    #pragma unroll
    for (int i = 0; i < MT * D / NTH; i++) {
        int e = tid + i * NTH;
        int row = e >> 6, d = e & 63;
        int idx = sidx[row];
        float x = gx[e];
        float q = cb[(long long)idx * D + d];
        float diff = __fsub_rn(q, x);
        out[rowbase * D + e] = __fadd_rn(x, diff);
        lsum = __fmaf_rn(diff, diff, lsum);
    }
    if (idx_off >= 0) out[idx_off + rowbase + tid] = (float)sidx[tid];

    #pragma unroll
    for (int off = 16; off; off >>= 1)
        lsum += __shfl_xor_sync(0xffffffffu, lsum, off);
    if (lane == 0) sred[wid] = lsum;
    __syncthreads();
    if (tid == 0) {
        float s = 0.f;
        #pragma unroll
        for (int w = 0; w < NTH / 32; w++) s += sred[w];
        g_part[blockIdx.x] = s;
    }
}

__global__ void vq_final(float* __restrict__ out, int nb,
                         long long loss_off, double inv_cnt) {
    __shared__ double sd[256];
    double s = 0.0;
    for (int i = threadIdx.x; i < nb; i += blockDim.x) s += (double)g_part[i];
    sd[threadIdx.x] = s;
    __syncthreads();
    for (int k = 128; k; k >>= 1) {
        if (threadIdx.x < k) sd[threadIdx.x] += sd[threadIdx.x + k];
        __syncthreads();
    }
    if (threadIdx.x == 0) {
        float m = (float)(sd[0] * inv_cnt);
        out[loss_off] = __fadd_rn(m, __fmul_rn(0.25f, m));
    }
}

extern "C" void kernel_launch(void* const* d_in, const int* in_sizes, int n_in,
                              void* d_out, int out_size) {
    const float* inp = (const float*)d_in[0];
    const float* cb  = (const float*)d_in[1];
    float* out = (float*)d_out;

    const int N = in_sizes[0] / D;                 // 131072
    const long long sq = (long long)N * D;
    long long loss_off = -1, idx_off = -1;
    if ((long long)out_size >= sq + 1)     loss_off = sq;
    if ((long long)out_size >= sq + 1 + N) idx_off  = sq + 1;

    const int nb = N / MT;                         // 512

    cudaFuncSetAttribute(vq_main, cudaFuncAttributeMaxDynamicSharedMemorySize, SMEM_DYN);

    vq_prep<<<(KCB * D + 255) / 256, 256>>>(cb);
    vq_main<<<nb, NTH, SMEM_DYN>>>(inp, cb, out, N, loss_off, idx_off);
    if (loss_off >= 0)
        vq_final<<<1, 256>>>(out, nb, loss_off, 1.0 / (double)((long long)N * D));
}